// round 1
// baseline (speedup 1.0000x reference)
#include <cuda_runtime.h>
#include <cstdint>

#define N_USERS 100000
#define N_ITEMS 60000
#define N_NODES 160000
#define D 64
#define D2 32              // D in float2 units
#define NNZ 1280000
#define EPS 0.1f
#define SCAN_BS 1024
#define NB_SCAN ((N_NODES + SCAN_BS - 1) / SCAN_BS)   // 157

// ---------------- scratch (static device globals; no allocation) -------------
__device__ int   g_cnt[N_NODES];
__device__ int   g_rowptr[N_NODES + 1];
__device__ int   g_cursor[N_NODES];
__device__ int   g_bsums[256];
__device__ int   g_cols_s[NNZ];
__device__ float g_vals_s[NNZ];
__device__ float g_ego1[(size_t)N_NODES * D];   // output of layer 0
__device__ float g_ego2[(size_t)N_NODES * D];   // output of layer 1

// ---------------- CSR build ---------------------------------------------------
__global__ void k_zero_cnt() {
    int i = blockIdx.x * blockDim.x + threadIdx.x;
    if (i < N_NODES) g_cnt[i] = 0;
}

__global__ void k_hist(const int* __restrict__ rows) {
    int e = blockIdx.x * blockDim.x + threadIdx.x;
    if (e < NNZ) atomicAdd(&g_cnt[rows[e]], 1);
}

// block-local exclusive scan of g_cnt -> g_rowptr (partial), block totals -> g_bsums
__global__ void k_scan1() {
    __shared__ int warp_sums[32];
    int i    = blockIdx.x * SCAN_BS + threadIdx.x;
    int lane = threadIdx.x & 31;
    int wid  = threadIdx.x >> 5;
    int v = (i < N_NODES) ? g_cnt[i] : 0;
    int s = v;
    #pragma unroll
    for (int d = 1; d < 32; d <<= 1) {
        int t = __shfl_up_sync(0xffffffffu, s, d);
        if (lane >= d) s += t;
    }
    if (lane == 31) warp_sums[wid] = s;
    __syncthreads();
    if (wid == 0) {
        int ws = warp_sums[lane];
        #pragma unroll
        for (int d = 1; d < 32; d <<= 1) {
            int t = __shfl_up_sync(0xffffffffu, ws, d);
            if (lane >= d) ws += t;
        }
        warp_sums[lane] = ws;
    }
    __syncthreads();
    int excl = s - v + (wid > 0 ? warp_sums[wid - 1] : 0);
    if (i < N_NODES) g_rowptr[i] = excl;
    if (threadIdx.x == SCAN_BS - 1) g_bsums[blockIdx.x] = warp_sums[31];
}

// serial exclusive scan of the 157 block sums (trivial work)
__global__ void k_scan2() {
    int running = 0;
    for (int b = 0; b < NB_SCAN; ++b) {
        int t = g_bsums[b];
        g_bsums[b] = running;
        running += t;
    }
    g_rowptr[N_NODES] = running;   // == NNZ
}

__global__ void k_scan3() {
    int i = blockIdx.x * SCAN_BS + threadIdx.x;
    if (i < N_NODES) {
        int r = g_rowptr[i] + g_bsums[blockIdx.x];
        g_rowptr[i] = r;
        g_cursor[i] = r;
    }
}

__global__ void k_scatter(const int* __restrict__ rows,
                          const int* __restrict__ cols,
                          const float* __restrict__ vals) {
    int e = blockIdx.x * blockDim.x + threadIdx.x;
    if (e < NNZ) {
        int r = rows[e];
        int p = atomicAdd(&g_cursor[r], 1);
        g_cols_s[p] = cols[e];
        g_vals_s[p] = vals[e];
    }
}

// ---------------- fused SpMM + noise-perturb + epilogue ----------------------
// One warp per output row; each lane owns 2 consecutive features (float2).
// x is addressed through (xu, xi): for layer 0 these are the two separate
// input embedding tables; for layers 1/2, xi = xu + N_USERS*D2 so the select
// reconstructs the single contiguous ego buffer with zero overhead.
template <int K>
__global__ void k_spmm(const float2* __restrict__ xu,
                       const float2* __restrict__ xi,
                       const float2* __restrict__ noise,   // already offset to layer K
                       const float2* __restrict__ prevA,   // used when K==2 (ego1)
                       const float2* __restrict__ prevB,   // used when K==2 (ego2)
                       float2* __restrict__ yout,          // used when K==0/1
                       float2* __restrict__ out2)          // d_out as float2
{
    int gw   = (blockIdx.x * blockDim.x + threadIdx.x) >> 5;
    int lane = threadIdx.x & 31;
    if (gw >= N_NODES) return;
    int row   = gw;
    int start = g_rowptr[row];
    int end   = g_rowptr[row + 1];

    float2 acc = make_float2(0.f, 0.f);
    for (int p = start; p < end; p += 32) {
        int cnt = min(32, end - p);
        int   c = 0;
        float v = 0.f;
        if (lane < cnt) {
            c = g_cols_s[p + lane];
            v = g_vals_s[p + lane];
        }
        for (int j = 0; j < cnt; ++j) {
            int   cc = __shfl_sync(0xffffffffu, c, j);
            float vv = __shfl_sync(0xffffffffu, v, j);
            const float2* xr = (cc < N_USERS) ? (xu + (size_t)cc * D2)
                                              : (xi + (size_t)(cc - N_USERS) * D2);
            float2 t = __ldg(xr + lane);
            acc.x += vv * t.x;
            acc.y += vv * t.y;
        }
    }

    // noise perturbation: ego += sign(ego) * (n / max(||n||, 1e-12)) * EPS
    size_t off = (size_t)row * D2 + lane;
    float2 nk = __ldg(noise + off);
    float ss = nk.x * nk.x + nk.y * nk.y;
    #pragma unroll
    for (int m = 16; m; m >>= 1) ss += __shfl_xor_sync(0xffffffffu, ss, m);
    float inv = EPS / fmaxf(sqrtf(ss), 1e-12f);
    float sx = (acc.x > 0.f) ? 1.f : ((acc.x < 0.f) ? -1.f : 0.f);
    float sy = (acc.y > 0.f) ? 1.f : ((acc.y < 0.f) ? -1.f : 0.f);
    acc.x += sx * nk.x * inv;
    acc.y += sy * nk.y * inv;

    if (K == 0) {
        yout[off] = acc;                                   // ego1
        out2[(size_t)N_NODES * D2 + off] = acc;            // CL region of output
    } else if (K == 1) {
        yout[off] = acc;                                   // ego2
    } else {
        float2 a = __ldg(prevA + off);
        float2 b = __ldg(prevB + off);
        const float third = 1.f / 3.f;
        float2 f = make_float2((a.x + b.x + acc.x) * third,
                               (a.y + b.y + acc.y) * third);
        out2[off] = f;                                     // final region of output
    }
}

// ---------------- launch ------------------------------------------------------
extern "C" void kernel_launch(void* const* d_in, const int* in_sizes, int n_in,
                              void* d_out, int out_size) {
    const float* user_emb = (const float*)d_in[0];
    const float* item_emb = (const float*)d_in[1];
    const float* adj_vals = (const float*)d_in[2];
    const float* noise    = (const float*)d_in[3];
    const int*   adj_rows = (const int*)d_in[4];
    const int*   adj_cols = (const int*)d_in[5];
    float2* out2 = (float2*)d_out;

    // --- build CSR from COO ---
    k_zero_cnt<<<(N_NODES + 255) / 256, 256>>>();
    k_hist<<<NNZ / 256, 256>>>(adj_rows);
    k_scan1<<<NB_SCAN, SCAN_BS>>>();
    k_scan2<<<1, 1>>>();
    k_scan3<<<NB_SCAN, SCAN_BS>>>();
    k_scatter<<<NNZ / 256, 256>>>(adj_rows, adj_cols, adj_vals);

    // --- fetch device-symbol addresses (host-side pointer math, no work) ---
    // Static __device__ arrays: take their addresses via kernels' linked symbols.
    // We can reference them directly by declaring matching host pointers through
    // cudaGetSymbolAddress once per call (cheap, not a stream op).
    static float2* ego1 = nullptr;
    static float2* ego2 = nullptr;
    if (!ego1) {
        void* p;
        cudaGetSymbolAddress(&p, g_ego1); ego1 = (float2*)p;
        cudaGetSymbolAddress(&p, g_ego2); ego2 = (float2*)p;
    }

    const float2* noise2 = (const float2*)noise;
    const int nwarps  = N_NODES;
    const int threads = 256;
    const int blocks  = (nwarps * 32 + threads - 1) / threads;  // 20000

    // layer 0: x = concat(user_emb, item_emb) via two base pointers
    k_spmm<0><<<blocks, threads>>>((const float2*)user_emb,
                                   (const float2*)item_emb,
                                   noise2 + (size_t)0 * N_NODES * D2,
                                   nullptr, nullptr, ego1, out2);
    // layer 1: x = ego1 (contiguous -> xi = xu + N_USERS*D2)
    k_spmm<1><<<blocks, threads>>>((const float2*)ego1,
                                   (const float2*)ego1 + (size_t)N_USERS * D2,
                                   noise2 + (size_t)1 * N_NODES * D2,
                                   nullptr, nullptr, ego2, out2);
    // layer 2: x = ego2; epilogue writes final = (ego1+ego2+ego3)/3
    k_spmm<2><<<blocks, threads>>>((const float2*)ego2,
                                   (const float2*)ego2 + (size_t)N_USERS * D2,
                                   noise2 + (size_t)2 * N_NODES * D2,
                                   (const float2*)ego1, (const float2*)ego2,
                                   nullptr, out2);
}